// round 4
// baseline (speedup 1.0000x reference)
#include <cuda_runtime.h>

typedef unsigned long long ull;

#define NB 16384
#define SLONG 100
#define SSHORT 10

// ---------------- f32x2 helpers (packed fp32 SIMD, sm_103a) ----------------
__device__ __forceinline__ ull pk2(float lo, float hi) {
    ull r; asm("mov.b64 %0, {%1, %2};" : "=l"(r) : "f"(lo), "f"(hi)); return r;
}
__device__ __forceinline__ ull bc2(float x) {
    ull r; asm("mov.b64 %0, {%1, %1};" : "=l"(r) : "f"(x)); return r;
}
__device__ __forceinline__ void up2(ull v, float& lo, float& hi) {
    asm("mov.b64 {%0, %1}, %2;" : "=f"(lo), "=f"(hi) : "l"(v));
}
__device__ __forceinline__ ull fma2(ull a, ull b, ull c) {
    ull d; asm("fma.rn.f32x2 %0, %1, %2, %3;" : "=l"(d) : "l"(a), "l"(b), "l"(c)); return d;
}

__device__ __forceinline__ float ftanh(float x) {
    float xc = fminf(fmaxf(x, -12.f), 12.f);
    float e = __expf(2.f * xc);
    return __fdividef(e - 1.f, e + 1.f);
}
__device__ __forceinline__ float fsig(float x) {
    return __fdividef(1.f, 1.f + __expf(-x));
}

// ---------------- device scratch (no allocations allowed) ----------------
__device__ ull  g_c1p[12 * 32];     // conv1 weights packed [ck][lane] -> (oc,oc+32)
__device__ ull  g_c2p[320 * 32];    // conv2
__device__ ull  g_c3p[448 * 32];    // conv3
__device__ ull  g_bn1sc[32], g_bn1sh[32];
__device__ ull  g_bn2sc[32], g_bn2sh[32];
__device__ ull  g_bn3sc[32], g_bn3sh[32];
__device__ float g_Wu[64];          // [c][i] 4x16  = proj_w @ Bm
__device__ float g_bu[16];          // proj_b @ Bm
__device__ ull  g_Mp[16 * 32];      // (Cm @ out_w) packed [j][lane]
__device__ ull  g_obp[32];          // out_b pairs
__device__ ull  g_g1p[128 * 32];    // g1_w packed [i][lane]
__device__ ull  g_g1b2[32];
__device__ ull  g_g2p[64 * 32];
__device__ ull  g_g2b2[32];
__device__ float g_hf[NB * 16];     // RNN final hidden state

// ---------------- kernel 1: pack / fold weights ----------------
__global__ void precompute_kernel(
    const float* __restrict__ c1w, const float* __restrict__ c1b,
    const float* __restrict__ c2w, const float* __restrict__ c2b,
    const float* __restrict__ c3w, const float* __restrict__ c3b,
    const float* __restrict__ bn1g, const float* __restrict__ bn1b,
    const float* __restrict__ bn2g, const float* __restrict__ bn2b,
    const float* __restrict__ bn3g, const float* __restrict__ bn3b,
    const float* __restrict__ pw,  const float* __restrict__ pb,
    const float* __restrict__ Bm,  const float* __restrict__ Cm,
    const float* __restrict__ ow,  const float* __restrict__ ob,
    const float* __restrict__ g1w, const float* __restrict__ g1b,
    const float* __restrict__ g2w, const float* __restrict__ g2b)
{
    int tid = blockIdx.x * blockDim.x + threadIdx.x;
    int nt  = gridDim.x * blockDim.x;
    const float S = rsqrtf(1.0f + 1e-5f);

    for (int i = tid; i < 12 * 32; i += nt) {
        int l = i & 31, ck = i >> 5;
        g_c1p[i] = pk2(c1w[l * 12 + ck], c1w[(l + 32) * 12 + ck]);
    }
    for (int i = tid; i < 320 * 32; i += nt) {
        int l = i & 31, ck = i >> 5;
        g_c2p[i] = pk2(c2w[l * 320 + ck], c2w[(l + 32) * 320 + ck]);
    }
    for (int i = tid; i < 448 * 32; i += nt) {
        int l = i & 31, ck = i >> 5;
        g_c3p[i] = pk2(c3w[l * 448 + ck], c3w[(l + 32) * 448 + ck]);
    }
    for (int i = tid; i < 32; i += nt) {
        float s0, s1;
        s0 = bn1g[i] * S; s1 = bn1g[i + 32] * S;
        g_bn1sc[i] = pk2(s0, s1);
        g_bn1sh[i] = pk2(fmaf(c1b[i], s0, bn1b[i]), fmaf(c1b[i + 32], s1, bn1b[i + 32]));
        s0 = bn2g[i] * S; s1 = bn2g[i + 32] * S;
        g_bn2sc[i] = pk2(s0, s1);
        g_bn2sh[i] = pk2(fmaf(c2b[i], s0, bn2b[i]), fmaf(c2b[i + 32], s1, bn2b[i + 32]));
        s0 = bn3g[i] * S; s1 = bn3g[i + 32] * S;
        g_bn3sc[i] = pk2(s0, s1);
        g_bn3sh[i] = pk2(fmaf(c3b[i], s0, bn3b[i]), fmaf(c3b[i + 32], s1, bn3b[i + 32]));
        g_obp[i]  = pk2(ob[i],  ob[i + 32]);
        g_g1b2[i] = pk2(g1b[i], g1b[i + 32]);
        g_g2b2[i] = pk2(g2b[i], g2b[i + 32]);
    }
    for (int i = tid; i < 64; i += nt) {           // W_u = proj_w(4,64) @ Bm(64,16)
        int c = i >> 4, j = i & 15;
        float s = 0.f;
        for (int h = 0; h < 64; h++) s = fmaf(pw[c * 64 + h], Bm[h * 16 + j], s);
        g_Wu[i] = s;
    }
    for (int i = tid; i < 16; i += nt) {           // b_u = proj_b @ Bm
        float s = 0.f;
        for (int h = 0; h < 64; h++) s = fmaf(pb[h], Bm[h * 16 + i], s);
        g_bu[i] = s;
    }
    for (int i = tid; i < 16 * 32; i += nt) {      // M = Cm(16,64) @ out_w(64,64)
        int j = i >> 5, l = i & 31;
        float lo = 0.f, hi = 0.f;
        for (int c = 0; c < 64; c++) {
            float cm = Cm[j * 64 + c];
            lo = fmaf(cm, ow[c * 64 + l], lo);
            hi = fmaf(cm, ow[c * 64 + l + 32], hi);
        }
        g_Mp[i] = pk2(lo, hi);
    }
    for (int i = tid; i < 128 * 32; i += nt) {
        int r = i >> 5, l = i & 31;
        g_g1p[i] = pk2(g1w[r * 64 + l], g1w[r * 64 + l + 32]);
    }
    for (int i = tid; i < 64 * 32; i += nt) {
        int r = i >> 5, l = i & 31;
        g_g2p[i] = pk2(g2w[r * 64 + l], g2w[r * 64 + l + 32]);
    }
}

// ---------------- kernel 2: RNN scan (half-warp per batch) ----------------
__global__ __launch_bounds__(256) void rnn_kernel(
    const float* __restrict__ x, const float* __restrict__ A)
{
    __shared__ __align__(16) float sx[8][800];
    int warp = threadIdx.x >> 5, lane = threadIdx.x & 31;
    int g = lane >> 4, li = lane & 15;
    int pairBase = (blockIdx.x * 8 + warp) * 2;

    const float* src = x + (size_t)pairBase * (SLONG * 4);
    float* dst = sx[warp];
    for (int i = lane; i < 800; i += 32) dst[i] = src[i];
    __syncwarp();

    float Ar[16];
#pragma unroll
    for (int j = 0; j < 16; j++) Ar[j] = __ldg(&A[li * 16 + j]);
    float wu0 = g_Wu[li], wu1 = g_Wu[16 + li], wu2 = g_Wu[32 + li], wu3 = g_Wu[48 + li];
    float bu = g_bu[li];

    const float* xr = &sx[warp][g * 400];
    float h = 0.f;
    for (int t = 0; t < SLONG; t++) {
        float4 xv = *(const float4*)(xr + t * 4);
        float u = bu;
        u = fmaf(xv.x, wu0, u); u = fmaf(xv.y, wu1, u);
        u = fmaf(xv.z, wu2, u); u = fmaf(xv.w, wu3, u);
        float a0 = u, a1 = 0.f, a2 = 0.f, a3 = 0.f;
#pragma unroll
        for (int j = 0; j < 16; j += 4) {
            a0 = fmaf(__shfl_sync(0xffffffffu, h, j + 0, 16), Ar[j + 0], a0);
            a1 = fmaf(__shfl_sync(0xffffffffu, h, j + 1, 16), Ar[j + 1], a1);
            a2 = fmaf(__shfl_sync(0xffffffffu, h, j + 2, 16), Ar[j + 2], a2);
            a3 = fmaf(__shfl_sync(0xffffffffu, h, j + 3, 16), Ar[j + 3], a3);
        }
        h = ftanh((a0 + a1) + (a2 + a3));
    }
    g_hf[(pairBase + g) * 16 + li] = h;
}

// ---------------- kernel 3: fused conv path + heads (1 warp / batch) ----------------
__global__ __launch_bounds__(128) void fused_kernel(
    const float* __restrict__ x,
    const float* __restrict__ h1w, const float* __restrict__ h1b,
    const float* __restrict__ h2w, const float* __restrict__ h2b,
    float* __restrict__ out)
{
    __shared__ float s_xs[4][40];
    __shared__ float s_actA[4][64 * 15];   // stride 15, data at t+2 (pad 2)
    __shared__ float s_actB[4][64 * 17];   // stride 17, data at t+3 (pad 3)
    __shared__ float s_comb[4][128];
    __shared__ float s_t1[4][64];
    __shared__ float s_fil[4][64];

    int w = threadIdx.x >> 5, lane = threadIdx.x & 31;
    int b = blockIdx.x * 4 + w;

    const float* xr = x + (size_t)b * (SLONG * 4) + (SLONG - SSHORT) * 4;
    for (int i = lane; i < 40; i += 32) s_xs[w][i] = xr[i];
    __syncwarp();

    ull acc[10];
#pragma unroll
    for (int t = 0; t < 10; t++) acc[t] = 0ull;

    // ---- conv1 (4 -> 64, k=3, pad 1) ----
#pragma unroll
    for (int c = 0; c < 4; c++) {
#pragma unroll
        for (int k = 0; k < 3; k++) {
            ull wv = __ldg(&g_c1p[(c * 3 + k) * 32 + lane]);
#pragma unroll
            for (int t = 0; t < 10; t++) {
                int idx = t + k - 1;
                if (idx >= 0 && idx < 10)
                    acc[t] = fma2(bc2(s_xs[w][idx * 4 + c]), wv, acc[t]);
            }
        }
    }
    {
        ull sc = g_bn1sc[lane], sh = g_bn1sh[lane];
        float* A0 = &s_actA[w][lane * 15];
        float* A1 = &s_actA[w][(lane + 32) * 15];
#pragma unroll
        for (int t = 0; t < 10; t++) {
            float lo, hi; up2(fma2(acc[t], sc, sh), lo, hi);
            A0[t + 2] = fmaxf(lo, 0.f);
            A1[t + 2] = fmaxf(hi, 0.f);
        }
        A0[0] = A0[1] = A0[12] = A0[13] = 0.f;
        A1[0] = A1[1] = A1[12] = A1[13] = 0.f;
    }
    __syncwarp();

    // ---- conv2 (64 -> 64, k=5, pad 2) ----
#pragma unroll
    for (int t = 0; t < 10; t++) acc[t] = 0ull;
    for (int c = 0; c < 64; c++) {
        const float* ar = &s_actA[w][c * 15];
        ull bb[14];
#pragma unroll
        for (int j = 0; j < 14; j++) bb[j] = bc2(ar[j]);
        const ull* wp = &g_c2p[c * 5 * 32 + lane];
#pragma unroll
        for (int k = 0; k < 5; k++) {
            ull wv = __ldg(&wp[k * 32]);
#pragma unroll
            for (int t = 0; t < 10; t++) acc[t] = fma2(bb[t + k], wv, acc[t]);
        }
    }
    {
        ull sc = g_bn2sc[lane], sh = g_bn2sh[lane];
        float* B0 = &s_actB[w][lane * 17];
        float* B1 = &s_actB[w][(lane + 32) * 17];
#pragma unroll
        for (int t = 0; t < 10; t++) {
            float lo, hi; up2(fma2(acc[t], sc, sh), lo, hi);
            B0[t + 3] = fmaxf(lo, 0.f);
            B1[t + 3] = fmaxf(hi, 0.f);
        }
        B0[0] = B0[1] = B0[2] = B0[13] = B0[14] = B0[15] = 0.f;
        B1[0] = B1[1] = B1[2] = B1[13] = B1[14] = B1[15] = 0.f;
    }
    __syncwarp();

    // ---- conv3 (64 -> 64, k=7, pad 3) + mean over time ----
#pragma unroll
    for (int t = 0; t < 10; t++) acc[t] = 0ull;
    for (int c = 0; c < 64; c++) {
        const float* ar = &s_actB[w][c * 17];
        ull bb[16];
#pragma unroll
        for (int j = 0; j < 16; j++) bb[j] = bc2(ar[j]);
        const ull* wp = &g_c3p[c * 7 * 32 + lane];
#pragma unroll
        for (int k = 0; k < 7; k++) {
            ull wv = __ldg(&wp[k * 32]);
#pragma unroll
            for (int t = 0; t < 10; t++) acc[t] = fma2(bb[t + k], wv, acc[t]);
        }
    }
    float sflo = 0.f, sfhi = 0.f;
    {
        ull sc = g_bn3sc[lane], sh = g_bn3sh[lane];
#pragma unroll
        for (int t = 0; t < 10; t++) {
            float lo, hi; up2(fma2(acc[t], sc, sh), lo, hi);
            sflo += fmaxf(lo, 0.f);
            sfhi += fmaxf(hi, 0.f);
        }
        sflo *= 0.1f; sfhi *= 0.1f;
    }
    s_comb[w][lane] = sflo;
    s_comb[w][lane + 32] = sfhi;

    // ---- long context: h_final @ M + out_b ----
    {
        float hreg[16];
#pragma unroll
        for (int j = 0; j < 16; j++) hreg[j] = __ldg(&g_hf[b * 16 + j]);
        ull a = g_obp[lane];
#pragma unroll
        for (int j = 0; j < 16; j++)
            a = fma2(bc2(hreg[j]), __ldg(&g_Mp[j * 32 + lane]), a);
        float lo, hi; up2(a, lo, hi);
        s_comb[w][64 + lane] = lo;
        s_comb[w][96 + lane] = hi;
    }
    __syncwarp();

    // ---- t1 = tanh(comb @ g1_w + g1_b) ----
    {
        ull a0 = g_g1b2[lane], a1 = 0ull;
#pragma unroll 8
        for (int i = 0; i < 128; i += 2) {
            a0 = fma2(bc2(s_comb[w][i]),     __ldg(&g_g1p[i * 32 + lane]),       a0);
            a1 = fma2(bc2(s_comb[w][i + 1]), __ldg(&g_g1p[(i + 1) * 32 + lane]), a1);
        }
        float l0, h0, l1, h1; up2(a0, l0, h0); up2(a1, l1, h1);
        s_t1[w][lane]      = ftanh(l0 + l1);
        s_t1[w][lane + 32] = ftanh(h0 + h1);
    }
    __syncwarp();

    // ---- gate = sigmoid(t1 @ g2_w + g2_b); filtered = sf * gate ----
    {
        ull a0 = g_g2b2[lane], a1 = 0ull;
#pragma unroll 8
        for (int i = 0; i < 64; i += 2) {
            a0 = fma2(bc2(s_t1[w][i]),     __ldg(&g_g2p[i * 32 + lane]),       a0);
            a1 = fma2(bc2(s_t1[w][i + 1]), __ldg(&g_g2p[(i + 1) * 32 + lane]), a1);
        }
        float l0, h0, l1, h1; up2(a0, l0, h0); up2(a1, l1, h1);
        s_fil[w][lane]      = sflo * fsig(l0 + l1);
        s_fil[w][lane + 32] = sfhi * fsig(h0 + h1);
    }
    __syncwarp();

    // ---- logits = relu(filtered @ h1_w + h1_b) @ h2_w + h2_b ----
    {
        float f0 = __ldg(&h1b[lane]), f1 = 0.f;
#pragma unroll 8
        for (int i = 0; i < 64; i += 2) {
            f0 = fmaf(s_fil[w][i],     __ldg(&h1w[i * 32 + lane]),       f0);
            f1 = fmaf(s_fil[w][i + 1], __ldg(&h1w[(i + 1) * 32 + lane]), f1);
        }
        float f = fmaxf(f0 + f1, 0.f);
        float p0 = f * __ldg(&h2w[lane * 3 + 0]);
        float p1 = f * __ldg(&h2w[lane * 3 + 1]);
        float p2 = f * __ldg(&h2w[lane * 3 + 2]);
#pragma unroll
        for (int off = 16; off; off >>= 1) {
            p0 += __shfl_xor_sync(0xffffffffu, p0, off);
            p1 += __shfl_xor_sync(0xffffffffu, p1, off);
            p2 += __shfl_xor_sync(0xffffffffu, p2, off);
        }
        if (lane == 0) {
            out[b * 3 + 0] = p0 + __ldg(&h2b[0]);
            out[b * 3 + 1] = p1 + __ldg(&h2b[1]);
            out[b * 3 + 2] = p2 + __ldg(&h2b[2]);
        }
    }
}

// ---------------- launch ----------------
extern "C" void kernel_launch(void* const* d_in, const int* in_sizes, int n_in,
                              void* d_out, int out_size)
{
    const float* x    = (const float*)d_in[0];
    const float* c1w  = (const float*)d_in[1];
    const float* c1b  = (const float*)d_in[2];
    const float* c2w  = (const float*)d_in[3];
    const float* c2b  = (const float*)d_in[4];
    const float* c3w  = (const float*)d_in[5];
    const float* c3b  = (const float*)d_in[6];
    const float* bn1g = (const float*)d_in[7];
    const float* bn1b = (const float*)d_in[8];
    const float* bn2g = (const float*)d_in[9];
    const float* bn2b = (const float*)d_in[10];
    const float* bn3g = (const float*)d_in[11];
    const float* bn3b = (const float*)d_in[12];
    const float* pw   = (const float*)d_in[13];
    const float* pb   = (const float*)d_in[14];
    const float* A    = (const float*)d_in[15];
    const float* Bm   = (const float*)d_in[16];
    const float* Cm   = (const float*)d_in[17];
    const float* ow   = (const float*)d_in[18];
    const float* ob   = (const float*)d_in[19];
    const float* g1w  = (const float*)d_in[20];
    const float* g1b  = (const float*)d_in[21];
    const float* g2w  = (const float*)d_in[22];
    const float* g2b  = (const float*)d_in[23];
    const float* h1w  = (const float*)d_in[24];
    const float* h1b  = (const float*)d_in[25];
    const float* h2w  = (const float*)d_in[26];
    const float* h2b  = (const float*)d_in[27];

    int Bn = in_sizes[0] / (SLONG * 4);   // 16384

    // Leave ~half the unified cache as L1D so the conv weight streams stay resident.
    static int carveout_set = 0;
    if (!carveout_set) {
        cudaFuncSetAttribute(fused_kernel, cudaFuncAttributePreferredSharedMemoryCarveout, 50);
        carveout_set = 1;
    }

    precompute_kernel<<<64, 256>>>(c1w, c1b, c2w, c2b, c3w, c3b,
                                   bn1g, bn1b, bn2g, bn2b, bn3g, bn3b,
                                   pw, pb, Bm, Cm, ow, ob,
                                   g1w, g1b, g2w, g2b);
    rnn_kernel<<<Bn / 16, 256>>>(x, A);
    fused_kernel<<<Bn / 4, 128>>>(x, h1w, h1b, h2w, h2b, (float*)d_out);
}

// round 6
// speedup vs baseline: 1.0010x; 1.0010x over previous
#include <cuda_runtime.h>

typedef unsigned long long ull;

#define NB 16384
#define SLONG 100
#define SSHORT 10

// ---------------- f32x2 helpers (packed fp32 SIMD, sm_103a) ----------------
__device__ __forceinline__ ull pk2(float lo, float hi) {
    ull r; asm("mov.b64 %0, {%1, %2};" : "=l"(r) : "f"(lo), "f"(hi)); return r;
}
__device__ __forceinline__ ull bc2(float x) {
    ull r; asm("mov.b64 %0, {%1, %1};" : "=l"(r) : "f"(x)); return r;
}
__device__ __forceinline__ void up2(ull v, float& lo, float& hi) {
    asm("mov.b64 {%0, %1}, %2;" : "=f"(lo), "=f"(hi) : "l"(v));
}
__device__ __forceinline__ ull fma2(ull a, ull b, ull c) {
    ull d; asm("fma.rn.f32x2 %0, %1, %2, %3;" : "=l"(d) : "l"(a), "l"(b), "l"(c)); return d;
}

__device__ __forceinline__ float ftanh(float x) {
    float xc = fminf(fmaxf(x, -12.f), 12.f);
    float e = __expf(2.f * xc);
    return __fdividef(e - 1.f, e + 1.f);
}
__device__ __forceinline__ float fsig(float x) {
    return __fdividef(1.f, 1.f + __expf(-x));
}

// ---------------- device scratch (no allocations allowed) ----------------
__device__ ull  g_c1p[12 * 32];     // conv1 weights packed [ck][lane] -> (oc,oc+32)
__device__ ull  g_c2p[320 * 32];    // conv2
__device__ ull  g_c3p[448 * 32];    // conv3
__device__ ull  g_bn1sc[32], g_bn1sh[32];
__device__ ull  g_bn2sc[32], g_bn2sh[32];
__device__ ull  g_bn3sc[32], g_bn3sh[32];
__device__ float g_Wu[64];          // [c][i] 4x16  = proj_w @ Bm
__device__ float g_bu[16];          // proj_b @ Bm
__device__ ull  g_Mp[16 * 32];      // (Cm @ out_w) packed [j][lane]
__device__ ull  g_obp[32];          // out_b pairs
__device__ ull  g_g1p[128 * 32];    // g1_w packed [i][lane]
__device__ ull  g_g1b2[32];
__device__ ull  g_g2p[64 * 32];
__device__ ull  g_g2b2[32];
__device__ float g_hf[NB * 16];     // RNN final hidden state

// ---------------- kernel 1: pack / fold weights ----------------
__global__ void precompute_kernel(
    const float* __restrict__ c1w, const float* __restrict__ c1b,
    const float* __restrict__ c2w, const float* __restrict__ c2b,
    const float* __restrict__ c3w, const float* __restrict__ c3b,
    const float* __restrict__ bn1g, const float* __restrict__ bn1b,
    const float* __restrict__ bn2g, const float* __restrict__ bn2b,
    const float* __restrict__ bn3g, const float* __restrict__ bn3b,
    const float* __restrict__ pw,  const float* __restrict__ pb,
    const float* __restrict__ Bm,  const float* __restrict__ Cm,
    const float* __restrict__ ow,  const float* __restrict__ ob,
    const float* __restrict__ g1w, const float* __restrict__ g1b,
    const float* __restrict__ g2w, const float* __restrict__ g2b)
{
    int tid = blockIdx.x * blockDim.x + threadIdx.x;
    int nt  = gridDim.x * blockDim.x;
    const float S = rsqrtf(1.0f + 1e-5f);

    for (int i = tid; i < 12 * 32; i += nt) {
        int l = i & 31, ck = i >> 5;
        g_c1p[i] = pk2(c1w[l * 12 + ck], c1w[(l + 32) * 12 + ck]);
    }
    for (int i = tid; i < 320 * 32; i += nt) {
        int l = i & 31, ck = i >> 5;
        g_c2p[i] = pk2(c2w[l * 320 + ck], c2w[(l + 32) * 320 + ck]);
    }
    for (int i = tid; i < 448 * 32; i += nt) {
        int l = i & 31, ck = i >> 5;
        g_c3p[i] = pk2(c3w[l * 448 + ck], c3w[(l + 32) * 448 + ck]);
    }
    for (int i = tid; i < 32; i += nt) {
        float s0, s1;
        s0 = bn1g[i] * S; s1 = bn1g[i + 32] * S;
        g_bn1sc[i] = pk2(s0, s1);
        g_bn1sh[i] = pk2(fmaf(c1b[i], s0, bn1b[i]), fmaf(c1b[i + 32], s1, bn1b[i + 32]));
        s0 = bn2g[i] * S; s1 = bn2g[i + 32] * S;
        g_bn2sc[i] = pk2(s0, s1);
        g_bn2sh[i] = pk2(fmaf(c2b[i], s0, bn2b[i]), fmaf(c2b[i + 32], s1, bn2b[i + 32]));
        s0 = bn3g[i] * S; s1 = bn3g[i + 32] * S;
        g_bn3sc[i] = pk2(s0, s1);
        g_bn3sh[i] = pk2(fmaf(c3b[i], s0, bn3b[i]), fmaf(c3b[i + 32], s1, bn3b[i + 32]));
        g_obp[i]  = pk2(ob[i],  ob[i + 32]);
        g_g1b2[i] = pk2(g1b[i], g1b[i + 32]);
        g_g2b2[i] = pk2(g2b[i], g2b[i + 32]);
    }
    for (int i = tid; i < 64; i += nt) {           // W_u = proj_w(4,64) @ Bm(64,16)
        int c = i >> 4, j = i & 15;
        float s = 0.f;
        for (int h = 0; h < 64; h++) s = fmaf(pw[c * 64 + h], Bm[h * 16 + j], s);
        g_Wu[i] = s;
    }
    for (int i = tid; i < 16; i += nt) {           // b_u = proj_b @ Bm
        float s = 0.f;
        for (int h = 0; h < 64; h++) s = fmaf(pb[h], Bm[h * 16 + i], s);
        g_bu[i] = s;
    }
    for (int i = tid; i < 16 * 32; i += nt) {      // M = Cm(16,64) @ out_w(64,64)
        int j = i >> 5, l = i & 31;
        float lo = 0.f, hi = 0.f;
        for (int c = 0; c < 64; c++) {
            float cm = Cm[j * 64 + c];
            lo = fmaf(cm, ow[c * 64 + l], lo);
            hi = fmaf(cm, ow[c * 64 + l + 32], hi);
        }
        g_Mp[i] = pk2(lo, hi);
    }
    for (int i = tid; i < 128 * 32; i += nt) {
        int r = i >> 5, l = i & 31;
        g_g1p[i] = pk2(g1w[r * 64 + l], g1w[r * 64 + l + 32]);
    }
    for (int i = tid; i < 64 * 32; i += nt) {
        int r = i >> 5, l = i & 31;
        g_g2p[i] = pk2(g2w[r * 64 + l], g2w[r * 64 + l + 32]);
    }
}

// ---------------- kernel 2: RNN scan (half-warp per batch) ----------------
__global__ __launch_bounds__(256) void rnn_kernel(
    const float* __restrict__ x, const float* __restrict__ A)
{
    __shared__ __align__(16) float sx[8][800];
    int warp = threadIdx.x >> 5, lane = threadIdx.x & 31;
    int g = lane >> 4, li = lane & 15;
    int pairBase = (blockIdx.x * 8 + warp) * 2;

    const float* src = x + (size_t)pairBase * (SLONG * 4);
    float* dst = sx[warp];
    for (int i = lane; i < 800; i += 32) dst[i] = src[i];
    __syncwarp();

    float Ar[16];
#pragma unroll
    for (int j = 0; j < 16; j++) Ar[j] = __ldg(&A[li * 16 + j]);
    float wu0 = g_Wu[li], wu1 = g_Wu[16 + li], wu2 = g_Wu[32 + li], wu3 = g_Wu[48 + li];
    float bu = g_bu[li];

    const float* xr = &sx[warp][g * 400];
    float h = 0.f;
    for (int t = 0; t < SLONG; t++) {
        float4 xv = *(const float4*)(xr + t * 4);
        float u = bu;
        u = fmaf(xv.x, wu0, u); u = fmaf(xv.y, wu1, u);
        u = fmaf(xv.z, wu2, u); u = fmaf(xv.w, wu3, u);
        float a0 = u, a1 = 0.f, a2 = 0.f, a3 = 0.f;
#pragma unroll
        for (int j = 0; j < 16; j += 4) {
            a0 = fmaf(__shfl_sync(0xffffffffu, h, j + 0, 16), Ar[j + 0], a0);
            a1 = fmaf(__shfl_sync(0xffffffffu, h, j + 1, 16), Ar[j + 1], a1);
            a2 = fmaf(__shfl_sync(0xffffffffu, h, j + 2, 16), Ar[j + 2], a2);
            a3 = fmaf(__shfl_sync(0xffffffffu, h, j + 3, 16), Ar[j + 3], a3);
        }
        h = ftanh((a0 + a1) + (a2 + a3));
    }
    g_hf[(pairBase + g) * 16 + li] = h;
}

// ---------------- kernel 3: fused conv path + heads (1 warp / batch) ----------------
__global__ __launch_bounds__(128) void fused_kernel(
    const float* __restrict__ x,
    const float* __restrict__ h1w, const float* __restrict__ h1b,
    const float* __restrict__ h2w, const float* __restrict__ h2b,
    float* __restrict__ out)
{
    __shared__ float s_xs[4][40];
    __shared__ float s_actA[4][64 * 15];   // stride 15, data at t+2 (pad 2)
    __shared__ float s_actB[4][64 * 17];   // stride 17, data at t+3 (pad 3)
    __shared__ float s_comb[4][128];
    __shared__ float s_t1[4][64];
    __shared__ float s_fil[4][64];

    int w = threadIdx.x >> 5, lane = threadIdx.x & 31;
    int b = blockIdx.x * 4 + w;

    const float* xr = x + (size_t)b * (SLONG * 4) + (SLONG - SSHORT) * 4;
    for (int i = lane; i < 40; i += 32) s_xs[w][i] = xr[i];
    __syncwarp();

    ull acc[10];
#pragma unroll
    for (int t = 0; t < 10; t++) acc[t] = 0ull;

    // ---- conv1 (4 -> 64, k=3, pad 1) ----
#pragma unroll
    for (int c = 0; c < 4; c++) {
#pragma unroll
        for (int k = 0; k < 3; k++) {
            ull wv = __ldg(&g_c1p[(c * 3 + k) * 32 + lane]);
#pragma unroll
            for (int t = 0; t < 10; t++) {
                int idx = t + k - 1;
                if (idx >= 0 && idx < 10)
                    acc[t] = fma2(bc2(s_xs[w][idx * 4 + c]), wv, acc[t]);
            }
        }
    }
    {
        ull sc = g_bn1sc[lane], sh = g_bn1sh[lane];
        float* A0 = &s_actA[w][lane * 15];
        float* A1 = &s_actA[w][(lane + 32) * 15];
#pragma unroll
        for (int t = 0; t < 10; t++) {
            float lo, hi; up2(fma2(acc[t], sc, sh), lo, hi);
            A0[t + 2] = fmaxf(lo, 0.f);
            A1[t + 2] = fmaxf(hi, 0.f);
        }
        A0[0] = A0[1] = A0[12] = A0[13] = 0.f;
        A1[0] = A1[1] = A1[12] = A1[13] = 0.f;
    }
    __syncwarp();

    // ---- conv2 (64 -> 64, k=5, pad 2) ----
#pragma unroll
    for (int t = 0; t < 10; t++) acc[t] = 0ull;
    for (int c = 0; c < 64; c++) {
        const float* ar = &s_actA[w][c * 15];
        ull bb[14];
#pragma unroll
        for (int j = 0; j < 14; j++) bb[j] = bc2(ar[j]);
        const ull* wp = &g_c2p[c * 5 * 32 + lane];
#pragma unroll
        for (int k = 0; k < 5; k++) {
            ull wv = __ldg(&wp[k * 32]);
#pragma unroll
            for (int t = 0; t < 10; t++) acc[t] = fma2(bb[t + k], wv, acc[t]);
        }
    }
    {
        ull sc = g_bn2sc[lane], sh = g_bn2sh[lane];
        float* B0 = &s_actB[w][lane * 17];
        float* B1 = &s_actB[w][(lane + 32) * 17];
#pragma unroll
        for (int t = 0; t < 10; t++) {
            float lo, hi; up2(fma2(acc[t], sc, sh), lo, hi);
            B0[t + 3] = fmaxf(lo, 0.f);
            B1[t + 3] = fmaxf(hi, 0.f);
        }
        B0[0] = B0[1] = B0[2] = B0[13] = B0[14] = B0[15] = 0.f;
        B1[0] = B1[1] = B1[2] = B1[13] = B1[14] = B1[15] = 0.f;
    }
    __syncwarp();

    // ---- conv3 (64 -> 64, k=7, pad 3) + mean over time ----
#pragma unroll
    for (int t = 0; t < 10; t++) acc[t] = 0ull;
    for (int c = 0; c < 64; c++) {
        const float* ar = &s_actB[w][c * 17];
        ull bb[16];
#pragma unroll
        for (int j = 0; j < 16; j++) bb[j] = bc2(ar[j]);
        const ull* wp = &g_c3p[c * 7 * 32 + lane];
#pragma unroll
        for (int k = 0; k < 7; k++) {
            ull wv = __ldg(&wp[k * 32]);
#pragma unroll
            for (int t = 0; t < 10; t++) acc[t] = fma2(bb[t + k], wv, acc[t]);
        }
    }
    float sflo = 0.f, sfhi = 0.f;
    {
        ull sc = g_bn3sc[lane], sh = g_bn3sh[lane];
#pragma unroll
        for (int t = 0; t < 10; t++) {
            float lo, hi; up2(fma2(acc[t], sc, sh), lo, hi);
            sflo += fmaxf(lo, 0.f);
            sfhi += fmaxf(hi, 0.f);
        }
        sflo *= 0.1f; sfhi *= 0.1f;
    }
    s_comb[w][lane] = sflo;
    s_comb[w][lane + 32] = sfhi;

    // ---- long context: h_final @ M + out_b ----
    {
        float hreg[16];
#pragma unroll
        for (int j = 0; j < 16; j++) hreg[j] = __ldg(&g_hf[b * 16 + j]);
        ull a = g_obp[lane];
#pragma unroll
        for (int j = 0; j < 16; j++)
            a = fma2(bc2(hreg[j]), __ldg(&g_Mp[j * 32 + lane]), a);
        float lo, hi; up2(a, lo, hi);
        s_comb[w][64 + lane] = lo;
        s_comb[w][96 + lane] = hi;
    }
    __syncwarp();

    // ---- t1 = tanh(comb @ g1_w + g1_b) ----
    {
        ull a0 = g_g1b2[lane], a1 = 0ull;
#pragma unroll 8
        for (int i = 0; i < 128; i += 2) {
            a0 = fma2(bc2(s_comb[w][i]),     __ldg(&g_g1p[i * 32 + lane]),       a0);
            a1 = fma2(bc2(s_comb[w][i + 1]), __ldg(&g_g1p[(i + 1) * 32 + lane]), a1);
        }
        float l0, h0, l1, h1; up2(a0, l0, h0); up2(a1, l1, h1);
        s_t1[w][lane]      = ftanh(l0 + l1);
        s_t1[w][lane + 32] = ftanh(h0 + h1);
    }
    __syncwarp();

    // ---- gate = sigmoid(t1 @ g2_w + g2_b); filtered = sf * gate ----
    {
        ull a0 = g_g2b2[lane], a1 = 0ull;
#pragma unroll 8
        for (int i = 0; i < 64; i += 2) {
            a0 = fma2(bc2(s_t1[w][i]),     __ldg(&g_g2p[i * 32 + lane]),       a0);
            a1 = fma2(bc2(s_t1[w][i + 1]), __ldg(&g_g2p[(i + 1) * 32 + lane]), a1);
        }
        float l0, h0, l1, h1; up2(a0, l0, h0); up2(a1, l1, h1);
        s_fil[w][lane]      = sflo * fsig(l0 + l1);
        s_fil[w][lane + 32] = sfhi * fsig(h0 + h1);
    }
    __syncwarp();

    // ---- logits = relu(filtered @ h1_w + h1_b) @ h2_w + h2_b ----
    {
        float f0 = __ldg(&h1b[lane]), f1 = 0.f;
#pragma unroll 8
        for (int i = 0; i < 64; i += 2) {
            f0 = fmaf(s_fil[w][i],     __ldg(&h1w[i * 32 + lane]),       f0);
            f1 = fmaf(s_fil[w][i + 1], __ldg(&h1w[(i + 1) * 32 + lane]), f1);
        }
        float f = fmaxf(f0 + f1, 0.f);
        float p0 = f * __ldg(&h2w[lane * 3 + 0]);
        float p1 = f * __ldg(&h2w[lane * 3 + 1]);
        float p2 = f * __ldg(&h2w[lane * 3 + 2]);
#pragma unroll
        for (int off = 16; off; off >>= 1) {
            p0 += __shfl_xor_sync(0xffffffffu, p0, off);
            p1 += __shfl_xor_sync(0xffffffffu, p1, off);
            p2 += __shfl_xor_sync(0xffffffffu, p2, off);
        }
        if (lane == 0) {
            out[b * 3 + 0] = p0 + __ldg(&h2b[0]);
            out[b * 3 + 1] = p1 + __ldg(&h2b[1]);
            out[b * 3 + 2] = p2 + __ldg(&h2b[2]);
        }
    }
}

// ---------------- launch ----------------
extern "C" void kernel_launch(void* const* d_in, const int* in_sizes, int n_in,
                              void* d_out, int out_size)
{
    const float* x    = (const float*)d_in[0];
    const float* c1w  = (const float*)d_in[1];
    const float* c1b  = (const float*)d_in[2];
    const float* c2w  = (const float*)d_in[3];
    const float* c2b  = (const float*)d_in[4];
    const float* c3w  = (const float*)d_in[5];
    const float* c3b  = (const float*)d_in[6];
    const float* bn1g = (const float*)d_in[7];
    const float* bn1b = (const float*)d_in[8];
    const float* bn2g = (const float*)d_in[9];
    const float* bn2b = (const float*)d_in[10];
    const float* bn3g = (const float*)d_in[11];
    const float* bn3b = (const float*)d_in[12];
    const float* pw   = (const float*)d_in[13];
    const float* pb   = (const float*)d_in[14];
    const float* A    = (const float*)d_in[15];
    const float* Bm   = (const float*)d_in[16];
    const float* Cm   = (const float*)d_in[17];
    const float* ow   = (const float*)d_in[18];
    const float* ob   = (const float*)d_in[19];
    const float* g1w  = (const float*)d_in[20];
    const float* g1b  = (const float*)d_in[21];
    const float* g2w  = (const float*)d_in[22];
    const float* g2b  = (const float*)d_in[23];
    const float* h1w  = (const float*)d_in[24];
    const float* h1b  = (const float*)d_in[25];
    const float* h2w  = (const float*)d_in[26];
    const float* h2b  = (const float*)d_in[27];

    int Bn = in_sizes[0] / (SLONG * 4);   // 16384

    // Leave ~half the unified cache as L1D so the conv weight streams stay resident.
    static int carveout_set = 0;
    if (!carveout_set) {
        cudaFuncSetAttribute(fused_kernel, cudaFuncAttributePreferredSharedMemoryCarveout, 50);
        carveout_set = 1;
    }

    precompute_kernel<<<64, 256>>>(c1w, c1b, c2w, c2b, c3w, c3b,
                                   bn1g, bn1b, bn2g, bn2b, bn3g, bn3b,
                                   pw, pb, Bm, Cm, ow, ob,
                                   g1w, g1b, g2w, g2b);
    rnn_kernel<<<Bn / 16, 256>>>(x, A);
    fused_kernel<<<Bn / 4, 128>>>(x, h1w, h1b, h2w, h2b, (float*)d_out);
}

// round 7
// speedup vs baseline: 1.0323x; 1.0312x over previous
#include <cuda_runtime.h>

typedef unsigned long long ull;

#define NB 16384
#define SLONG 100
#define SSHORT 10

// ---------------- f32x2 helpers ----------------
__device__ __forceinline__ ull pk2(float lo, float hi) {
    ull r; asm("mov.b64 %0, {%1, %2};" : "=l"(r) : "f"(lo), "f"(hi)); return r;
}
__device__ __forceinline__ ull bc2(float x) {
    ull r; asm("mov.b64 %0, {%1, %1};" : "=l"(r) : "f"(x)); return r;
}
__device__ __forceinline__ void up2(ull v, float& lo, float& hi) {
    asm("mov.b64 {%0, %1}, %2;" : "=f"(lo), "=f"(hi) : "l"(v));
}
__device__ __forceinline__ ull fma2(ull a, ull b, ull c) {
    ull d; asm("fma.rn.f32x2 %0, %1, %2, %3;" : "=l"(d) : "l"(a), "l"(b), "l"(c)); return d;
}
__device__ __forceinline__ ull add2(ull a, ull b) {
    ull d; asm("add.rn.f32x2 %0, %1, %2;" : "=l"(d) : "l"(a), "l"(b)); return d;
}
__device__ __forceinline__ ull mul2(ull a, ull b) {
    ull d; asm("mul.rn.f32x2 %0, %1, %2;" : "=l"(d) : "l"(a), "l"(b)); return d;
}
__device__ __forceinline__ ull relu2(ull v) {
    float lo, hi; up2(v, lo, hi);
    return pk2(fmaxf(lo, 0.f), fmaxf(hi, 0.f));
}
__device__ __forceinline__ float ftanh(float x) {
    float xc = fminf(fmaxf(x, -12.f), 12.f);
    float e = __expf(2.f * xc);
    return __fdividef(e - 1.f, e + 1.f);
}
__device__ __forceinline__ float fsig(float x) {
    return __fdividef(1.f, 1.f + __expf(-x));
}
__device__ __forceinline__ ull tanh2(ull v) {
    float lo, hi; up2(v, lo, hi);
    return pk2(ftanh(lo), ftanh(hi));
}
__device__ __forceinline__ ull sig2(ull v) {
    float lo, hi; up2(v, lo, hi);
    return pk2(fsig(lo), fsig(hi));
}

// ---------------- device scratch ----------------
__device__ float g_c1s[12 * 64];     // [c*3+k][oc] scalar
__device__ float g_c2s[320 * 64];    // [c*5+k][oc]
__device__ float g_c3s[448 * 64];    // [c*7+k][oc]
__device__ ull   g_bn1scd[64], g_bn1shd[64];
__device__ ull   g_bn2scd[64], g_bn2shd[64];
__device__ ull   g_bn3scd[64], g_bn3shd[64];
__device__ float g_Wu[64];           // proj_w @ Bm  [c][i] 4x16
__device__ float g_bu[16];           // proj_b @ Bm
__device__ ull   g_Md[16 * 64];      // dup (Cm@out_w)[j][oc]
__device__ ull   g_obd[64];
__device__ ull   g_g1d[128 * 64];    // dup g1_w
__device__ ull   g_g1bd[64];
__device__ ull   g_g2d[64 * 64];
__device__ ull   g_g2bd[64];
__device__ ull   g_h1d[64 * 32];
__device__ ull   g_h1bd[32];
__device__ ull   g_h2d[32 * 3];
__device__ float g_hf[NB * 16];

// ---------------- kernel 1: pack / fold ----------------
__global__ void precompute_kernel(
    const float* __restrict__ c1w, const float* __restrict__ c1b,
    const float* __restrict__ c2w, const float* __restrict__ c2b,
    const float* __restrict__ c3w, const float* __restrict__ c3b,
    const float* __restrict__ bn1g, const float* __restrict__ bn1b,
    const float* __restrict__ bn2g, const float* __restrict__ bn2b,
    const float* __restrict__ bn3g, const float* __restrict__ bn3b,
    const float* __restrict__ pw,  const float* __restrict__ pb,
    const float* __restrict__ Bm,  const float* __restrict__ Cm,
    const float* __restrict__ ow,  const float* __restrict__ ob,
    const float* __restrict__ g1w, const float* __restrict__ g1b,
    const float* __restrict__ g2w, const float* __restrict__ g2b,
    const float* __restrict__ h1w, const float* __restrict__ h1b,
    const float* __restrict__ h2w)
{
    int tid = blockIdx.x * blockDim.x + threadIdx.x;
    int nt  = gridDim.x * blockDim.x;
    const float S = rsqrtf(1.0f + 1e-5f);

    for (int i = tid; i < 12 * 64; i += nt) {
        int oc = i & 63, ck = i >> 6;
        g_c1s[ck * 64 + oc] = c1w[oc * 12 + ck];
    }
    for (int i = tid; i < 320 * 64; i += nt) {
        int oc = i & 63, ck = i >> 6;
        g_c2s[ck * 64 + oc] = c2w[oc * 320 + ck];
    }
    for (int i = tid; i < 448 * 64; i += nt) {
        int oc = i & 63, ck = i >> 6;
        g_c3s[ck * 64 + oc] = c3w[oc * 448 + ck];
    }
    for (int i = tid; i < 64; i += nt) {
        float s;
        s = bn1g[i] * S; g_bn1scd[i] = bc2(s); g_bn1shd[i] = bc2(fmaf(c1b[i], s, bn1b[i]));
        s = bn2g[i] * S; g_bn2scd[i] = bc2(s); g_bn2shd[i] = bc2(fmaf(c2b[i], s, bn2b[i]));
        s = bn3g[i] * S; g_bn3scd[i] = bc2(s); g_bn3shd[i] = bc2(fmaf(c3b[i], s, bn3b[i]));
        g_obd[i]  = bc2(ob[i]);
        g_g1bd[i] = bc2(g1b[i]);
        g_g2bd[i] = bc2(g2b[i]);
    }
    for (int i = tid; i < 64; i += nt) {          // W_u = proj_w(4,64) @ Bm(64,16)
        int c = i >> 4, j = i & 15;
        float s = 0.f;
        for (int h = 0; h < 64; h++) s = fmaf(pw[c * 64 + h], Bm[h * 16 + j], s);
        g_Wu[i] = s;
    }
    for (int i = tid; i < 16; i += nt) {
        float s = 0.f;
        for (int h = 0; h < 64; h++) s = fmaf(pb[h], Bm[h * 16 + i], s);
        g_bu[i] = s;
    }
    for (int i = tid; i < 16 * 64; i += nt) {     // M = Cm(16,64) @ out_w(64,64)
        int j = i >> 6, oc = i & 63;
        float s = 0.f;
        for (int c = 0; c < 64; c++) s = fmaf(Cm[j * 64 + c], ow[c * 64 + oc], s);
        g_Md[i] = bc2(s);
    }
    for (int i = tid; i < 128 * 64; i += nt) g_g1d[i] = bc2(g1w[i]);
    for (int i = tid; i < 64 * 64;  i += nt) g_g2d[i] = bc2(g2w[i]);
    for (int i = tid; i < 64 * 32;  i += nt) g_h1d[i] = bc2(h1w[i]);
    for (int i = tid; i < 32;       i += nt) g_h1bd[i] = bc2(h1b[i]);
    for (int i = tid; i < 32 * 3;   i += nt) g_h2d[i] = bc2(h2w[i]);
}

// ---------------- kernel 2: RNN scan (half-warp per batch) ----------------
__global__ __launch_bounds__(256) void rnn_kernel(
    const float* __restrict__ x, const float* __restrict__ A)
{
    __shared__ __align__(16) float sx[8][800];
    int warp = threadIdx.x >> 5, lane = threadIdx.x & 31;
    int g = lane >> 4, li = lane & 15;
    int pairBase = (blockIdx.x * 8 + warp) * 2;

    const float* src = x + (size_t)pairBase * (SLONG * 4);
    float* dst = sx[warp];
    for (int i = lane; i < 800; i += 32) dst[i] = src[i];
    __syncwarp();

    float Ar[16];
#pragma unroll
    for (int j = 0; j < 16; j++) Ar[j] = __ldg(&A[li * 16 + j]);
    float wu0 = g_Wu[li], wu1 = g_Wu[16 + li], wu2 = g_Wu[32 + li], wu3 = g_Wu[48 + li];
    float bu = g_bu[li];

    const float* xr = &sx[warp][g * 400];
    float h = 0.f;
    for (int t = 0; t < SLONG; t++) {
        float4 xv = *(const float4*)(xr + t * 4);
        float u = bu;
        u = fmaf(xv.x, wu0, u); u = fmaf(xv.y, wu1, u);
        u = fmaf(xv.z, wu2, u); u = fmaf(xv.w, wu3, u);
        float a0 = u, a1 = 0.f, a2 = 0.f, a3 = 0.f;
#pragma unroll
        for (int j = 0; j < 16; j += 4) {
            a0 = fmaf(__shfl_sync(0xffffffffu, h, j + 0, 16), Ar[j + 0], a0);
            a1 = fmaf(__shfl_sync(0xffffffffu, h, j + 1, 16), Ar[j + 1], a1);
            a2 = fmaf(__shfl_sync(0xffffffffu, h, j + 2, 16), Ar[j + 2], a2);
            a3 = fmaf(__shfl_sync(0xffffffffu, h, j + 3, 16), Ar[j + 3], a3);
        }
        h = ftanh((a0 + a1) + (a2 + a3));
    }
    g_hf[(pairBase + g) * 16 + li] = h;
}

// ---------------- kernel 3: fused conv + heads, batch-pair f32x2 packing ----
// One warp = batches (b0, b0+1) as the two f32x2 lanes; lane covers oc=lane and oc=lane+32.
// Per-warp ull layout: x 40 | actA 704 (stride 11) | actB 704 | comb 128 | fil 64
#define OFF_X   0
#define OFF_A   40
#define OFF_B   744
#define OFF_CMB 1448
#define OFF_FIL 1576
#define WARP_ULL 1640
#define SMEM_BYTES (4 * WARP_ULL * 8)

__global__ __launch_bounds__(128) void fused_kernel(
    const float* __restrict__ x,
    const float* __restrict__ h2b,
    float* __restrict__ out)
{
    extern __shared__ ull dsm[];
    int w = threadIdx.x >> 5, lane = threadIdx.x & 31;
    ull* S = dsm + w * WARP_ULL;

    int b0 = (blockIdx.x * 4 + w) * 2;
    const float* xA = x + (size_t)b0 * (SLONG * 4) + (SLONG - SSHORT) * 4;
    const float* xB = xA + SLONG * 4;
    for (int i = lane; i < 40; i += 32)
        S[OFF_X + i] = pk2(__ldg(xA + i), __ldg(xB + i));
    __syncwarp();

    ull a0[10], a1[10];
#pragma unroll
    for (int t = 0; t < 10; t++) { a0[t] = 0ull; a1[t] = 0ull; }

    // ---- conv1 (4 -> 64, k=3, pad 1) ----
#pragma unroll
    for (int c = 0; c < 4; c++) {
        ull bb[10];
#pragma unroll
        for (int t = 0; t < 10; t++) bb[t] = S[OFF_X + t * 4 + c];
#pragma unroll
        for (int k = 0; k < 3; k++) {
            ull w0 = bc2(__ldg(&g_c1s[(c * 3 + k) * 64 + lane]));
            ull w1 = bc2(__ldg(&g_c1s[(c * 3 + k) * 64 + lane + 32]));
#pragma unroll
            for (int t = 0; t < 10; t++) {
                int idx = t + k - 1;
                if (idx >= 0 && idx < 10) {
                    a0[t] = fma2(bb[idx], w0, a0[t]);
                    a1[t] = fma2(bb[idx], w1, a1[t]);
                }
            }
        }
    }
    {
        ull sc0 = g_bn1scd[lane],      sh0 = g_bn1shd[lane];
        ull sc1 = g_bn1scd[lane + 32], sh1 = g_bn1shd[lane + 32];
        ull* A0 = S + OFF_A + lane * 11;
        ull* A1 = S + OFF_A + (lane + 32) * 11;
#pragma unroll
        for (int t = 0; t < 10; t++) {
            A0[t] = relu2(fma2(a0[t], sc0, sh0));
            A1[t] = relu2(fma2(a1[t], sc1, sh1));
            a0[t] = 0ull; a1[t] = 0ull;
        }
    }
    __syncwarp();

    // ---- conv2 (64 -> 64, k=5, pad 2), pad-pruned ----
#pragma unroll 2
    for (int c = 0; c < 64; c++) {
        const ull* ar = S + OFF_A + c * 11;
        ull bb[10];
#pragma unroll
        for (int j = 0; j < 10; j++) bb[j] = ar[j];
        const float* wp = g_c2s + c * 5 * 64 + lane;
#pragma unroll
        for (int k = 0; k < 5; k++) {
            ull w0 = bc2(__ldg(wp + k * 64));
            ull w1 = bc2(__ldg(wp + k * 64 + 32));
#pragma unroll
            for (int t = 0; t < 10; t++) {
                int idx = t + k - 2;
                if (idx >= 0 && idx < 10) {
                    a0[t] = fma2(bb[idx], w0, a0[t]);
                    a1[t] = fma2(bb[idx], w1, a1[t]);
                }
            }
        }
    }
    {
        ull sc0 = g_bn2scd[lane],      sh0 = g_bn2shd[lane];
        ull sc1 = g_bn2scd[lane + 32], sh1 = g_bn2shd[lane + 32];
        ull* B0 = S + OFF_B + lane * 11;
        ull* B1 = S + OFF_B + (lane + 32) * 11;
#pragma unroll
        for (int t = 0; t < 10; t++) {
            B0[t] = relu2(fma2(a0[t], sc0, sh0));
            B1[t] = relu2(fma2(a1[t], sc1, sh1));
            a0[t] = 0ull; a1[t] = 0ull;
        }
    }
    __syncwarp();

    // ---- conv3 (64 -> 64, k=7, pad 3) + mean, pad-pruned ----
#pragma unroll 2
    for (int c = 0; c < 64; c++) {
        const ull* ar = S + OFF_B + c * 11;
        ull bb[10];
#pragma unroll
        for (int j = 0; j < 10; j++) bb[j] = ar[j];
        const float* wp = g_c3s + c * 7 * 64 + lane;
#pragma unroll
        for (int k = 0; k < 7; k++) {
            ull w0 = bc2(__ldg(wp + k * 64));
            ull w1 = bc2(__ldg(wp + k * 64 + 32));
#pragma unroll
            for (int t = 0; t < 10; t++) {
                int idx = t + k - 3;
                if (idx >= 0 && idx < 10) {
                    a0[t] = fma2(bb[idx], w0, a0[t]);
                    a1[t] = fma2(bb[idx], w1, a1[t]);
                }
            }
        }
    }
    ull sf0, sf1;
    {
        ull sc0 = g_bn3scd[lane],      sh0 = g_bn3shd[lane];
        ull sc1 = g_bn3scd[lane + 32], sh1 = g_bn3shd[lane + 32];
        ull s0 = 0ull, s1 = 0ull;
#pragma unroll
        for (int t = 0; t < 10; t++) {
            s0 = add2(s0, relu2(fma2(a0[t], sc0, sh0)));
            s1 = add2(s1, relu2(fma2(a1[t], sc1, sh1)));
        }
        ull tenth = bc2(0.1f);
        sf0 = mul2(s0, tenth);
        sf1 = mul2(s1, tenth);
        S[OFF_CMB + lane]      = sf0;
        S[OFF_CMB + lane + 32] = sf1;
    }

    // ---- long context: h_final @ M + out_b ----
    {
        const float* hA = g_hf + (size_t)b0 * 16;
        ull l0 = g_obd[lane], l1 = g_obd[lane + 32];
#pragma unroll
        for (int j = 0; j < 16; j++) {
            ull hp = pk2(__ldg(hA + j), __ldg(hA + 16 + j));
            l0 = fma2(hp, __ldg(&g_Md[j * 64 + lane]),      l0);
            l1 = fma2(hp, __ldg(&g_Md[j * 64 + lane + 32]), l1);
        }
        S[OFF_CMB + 64 + lane] = l0;
        S[OFF_CMB + 96 + lane] = l1;
    }
    __syncwarp();

    // ---- t1 = tanh(comb @ g1_w + g1_b)  (t1 kept in fil slot temporarily) ----
    {
        ull t0 = g_g1bd[lane], t1v = g_g1bd[lane + 32];
#pragma unroll 8
        for (int i = 0; i < 128; i++) {
            ull cb = S[OFF_CMB + i];
            t0  = fma2(cb, __ldg(&g_g1d[i * 64 + lane]),      t0);
            t1v = fma2(cb, __ldg(&g_g1d[i * 64 + lane + 32]), t1v);
        }
        S[OFF_FIL + lane]      = tanh2(t0);
        S[OFF_FIL + lane + 32] = tanh2(t1v);
    }
    __syncwarp();

    // ---- gate = sigmoid(t1 @ g2_w + g2_b); filtered = sf * gate ----
    ull f0, f1;
    {
        ull q0 = g_g2bd[lane], q1 = g_g2bd[lane + 32];
#pragma unroll 8
        for (int i = 0; i < 64; i++) {
            ull tv = S[OFF_FIL + i];
            q0 = fma2(tv, __ldg(&g_g2d[i * 64 + lane]),      q0);
            q1 = fma2(tv, __ldg(&g_g2d[i * 64 + lane + 32]), q1);
        }
        f0 = mul2(sf0, sig2(q0));
        f1 = mul2(sf1, sig2(q1));
    }
    __syncwarp();
    S[OFF_FIL + lane]      = f0;
    S[OFF_FIL + lane + 32] = f1;
    __syncwarp();

    // ---- logits = relu(filtered @ h1_w + h1_b) @ h2_w + h2_b ----
    {
        ull acc = g_h1bd[lane];
#pragma unroll 8
        for (int i = 0; i < 64; i++)
            acc = fma2(S[OFF_FIL + i], __ldg(&g_h1d[i * 32 + lane]), acc);
        ull f = relu2(acc);
        float pl[3], ph[3];
#pragma unroll
        for (int r = 0; r < 3; r++) {
            ull p = mul2(f, g_h2d[lane * 3 + r]);
            up2(p, pl[r], ph[r]);
#pragma unroll
            for (int off = 16; off; off >>= 1) {
                pl[r] += __shfl_xor_sync(0xffffffffu, pl[r], off);
                ph[r] += __shfl_xor_sync(0xffffffffu, ph[r], off);
            }
        }
        if (lane == 0) {
#pragma unroll
            for (int r = 0; r < 3; r++) {
                float hb = __ldg(&h2b[r]);
                out[b0 * 3 + r]       = pl[r] + hb;
                out[(b0 + 1) * 3 + r] = ph[r] + hb;
            }
        }
    }
}

// ---------------- launch ----------------
extern "C" void kernel_launch(void* const* d_in, const int* in_sizes, int n_in,
                              void* d_out, int out_size)
{
    const float* x    = (const float*)d_in[0];
    const float* c1w  = (const float*)d_in[1];
    const float* c1b  = (const float*)d_in[2];
    const float* c2w  = (const float*)d_in[3];
    const float* c2b  = (const float*)d_in[4];
    const float* c3w  = (const float*)d_in[5];
    const float* c3b  = (const float*)d_in[6];
    const float* bn1g = (const float*)d_in[7];
    const float* bn1b = (const float*)d_in[8];
    const float* bn2g = (const float*)d_in[9];
    const float* bn2b = (const float*)d_in[10];
    const float* bn3g = (const float*)d_in[11];
    const float* bn3b = (const float*)d_in[12];
    const float* pw   = (const float*)d_in[13];
    const float* pb   = (const float*)d_in[14];
    const float* A    = (const float*)d_in[15];
    const float* Bm   = (const float*)d_in[16];
    const float* Cm   = (const float*)d_in[17];
    const float* ow   = (const float*)d_in[18];
    const float* ob   = (const float*)d_in[19];
    const float* g1w  = (const float*)d_in[20];
    const float* g1b  = (const float*)d_in[21];
    const float* g2w  = (const float*)d_in[22];
    const float* g2b  = (const float*)d_in[23];
    const float* h1w  = (const float*)d_in[24];
    const float* h1b  = (const float*)d_in[25];
    const float* h2w  = (const float*)d_in[26];
    const float* h2b  = (const float*)d_in[27];

    int Bn = in_sizes[0] / (SLONG * 4);   // 16384

    static int attr_set = 0;
    if (!attr_set) {
        cudaFuncSetAttribute(fused_kernel, cudaFuncAttributeMaxDynamicSharedMemorySize, SMEM_BYTES);
        cudaFuncSetAttribute(fused_kernel, cudaFuncAttributePreferredSharedMemoryCarveout, 50);
        attr_set = 1;
    }

    precompute_kernel<<<64, 256>>>(c1w, c1b, c2w, c2b, c3w, c3b,
                                   bn1g, bn1b, bn2g, bn2b, bn3g, bn3b,
                                   pw, pb, Bm, Cm, ow, ob,
                                   g1w, g1b, g2w, g2b, h1w, h1b, h2w);
    rnn_kernel<<<Bn / 16, 256>>>(x, A);
    fused_kernel<<<Bn / 8, 128, SMEM_BYTES>>>(x, h2b, (float*)d_out);
}